// round 7
// baseline (speedup 1.0000x reference)
#include <cuda_runtime.h>
#include <cuda_fp16.h>
#include <cstdint>

// Problem constants (fixed per reference)
#define Bn 8
#define Hn 1080
#define Wn 1920
constexpr int HW   = Hn * Wn;          // 2,073,600
constexpr int BHW  = Bn * HW;          // 16,588,800
constexpr int WP   = Wn / 2;           // 960 pair-cells per row
constexpr int LAT1 = Hn * WP;          // 1,036,800 pair-cells per lattice (per slice)

// Per-slice pair-cell lattices (REUSED for all 8 batches -> stays L2-resident):
// each 16B cell = [vx0,vy0,w0,pad | vx1,vy1,w1,pad] (8 x f16)
// Lattice 0 (even parity): pair k covers corners (2k, 2k+1)
// Lattice 1 (odd parity):  pair k covers corners (2k+1, 2k+2)
//
// INVARIANT: lattice is all-zero at slice entry. Zero-init at module load
// provides the first replay; normalize_kernel re-zeroes every half-cell it
// reads (each half-cell has exactly one reader), restoring the invariant for
// the next slice AND the next graph replay. The single never-read half-cell
// (odd lattice, pair WP-1 hi) only ever receives explicit zero deposits.
__device__ float4        g_lat[2 * LAT1];   // 33.2 MB — fits L2 (126 MB)
__device__ unsigned char g_mask[BHW];       // count>0 flag (whole image)
__device__ int           g_holes[BHW];      // compacted hole indices (global index)
__device__ int           g_hole_count;

// --- bit reinterpretation helpers (header-portable) ------------------------
__device__ __forceinline__ unsigned h2_to_u32(__half2 h) {
    union { __half2 h; unsigned u; } cvt; cvt.h = h; return cvt.u;
}
__device__ __forceinline__ __half2 u32_to_h2(unsigned u) {
    union { unsigned u; __half2 h; } cvt; cvt.u = u; return cvt.h;
}

// One 16B vectorized f16x2 reduction: deposits (vx,vy,w) to TWO adjacent corners.
__device__ __forceinline__ void red_add_v4_f16x2(float4* p, unsigned r0, unsigned r1,
                                                 unsigned r2, unsigned r3) {
    asm volatile("red.global.add.noftz.v4.f16x2 [%0], {%1, %2, %3, %4};"
                 :: "l"(p), "r"(r0), "r"(r1), "r"(r2), "r"(r3) : "memory");
}

// ---------------------------------------------------------------------------
// 0) Reset the hole counter (once per replay).
// ---------------------------------------------------------------------------
__global__ void reset_kernel() { g_hole_count = 0; }

// ---------------------------------------------------------------------------
// 1) Forward splat for ONE batch slice: 2 vector REDs per pixel (one per
//    target row), each depositing to both x-adjacent corners at once.
//    flow/depth pointers are pre-offset to this batch.
// ---------------------------------------------------------------------------
__global__ void splat_kernel(const float* __restrict__ flow,
                             const float* __restrict__ depth) {
    const int p = blockIdx.x * blockDim.x + threadIdx.x;   // [0, HW)
    const int y = p / Wn;
    const int x = p - y * Wn;

    const float fx = flow[p];
    const float fy = flow[HW + p];

    const float x2 = (float)x + fx;
    const float y2 = (float)y + fy;

    // Invalid pixels deposit exactly 0 in the reference -> skip.
    if (!(x2 >= 0.0f && x2 <= (float)(Wn - 1) &&
          y2 >= 0.0f && y2 <= (float)(Hn - 1)))
        return;

    const float w  = depth[p];
    const float vx = -fx * w;
    const float vy = -fy * w;

    // floor == trunc (non-negative by validity check)
    const int ixL = (int)x2;
    const int iyT = (int)y2;
    const int ixR = min(ixL + 1, Wn - 1);
    const int iyB = min(iyT + 1, Hn - 1);

    // Payload: lo half -> corner ixL, hi half -> corner ixR.
    // ixR==ixL (x2 == W-1 exactly): double lo payload, zero hi
    // (rn(2v) == 2*rn(v) in f16, bit-identical to two adds).
    const bool  dup = (ixR == ixL);
    const float m   = dup ? 2.0f : 1.0f;

    const unsigned r0 = h2_to_u32(__floats2half2_rn(vx * m, vy * m));
    const unsigned r1 = h2_to_u32(__floats2half2_rn(w * m, 0.0f));
    const unsigned r2 = dup ? 0u : h2_to_u32(__floats2half2_rn(vx, vy));
    const unsigned r3 = dup ? 0u : h2_to_u32(__floats2half2_rn(w, 0.0f));

    const int s  = ixL & 1;        // lattice parity
    const int kp = ixL >> 1;       // pair index

    float4* lat = g_lat + (size_t)s * LAT1 + kp;
    red_add_v4_f16x2(lat + iyT * WP, r0, r1, r2, r3);
    red_add_v4_f16x2(lat + iyB * WP, r0, r1, r2, r3);
}

// ---------------------------------------------------------------------------
// 2) Normalize ONE batch slice + RE-ZERO the lattice cells read.
//    Each half-cell has exactly one reader thread -> the zero-writeback is
//    race-free and restores the all-zero invariant for the next slice/replay.
// ---------------------------------------------------------------------------
__global__ void normalize_kernel(float* __restrict__ out, int gbase) {
    const int p = blockIdx.x * blockDim.x + threadIdx.x;   // [0, HW)
    const int y = p / Wn;
    const int x = p - y * Wn;

    uint2* lat2 = (uint2*)g_lat;   // one uint2 = one 8B half-cell
    const size_t rowc = (size_t)y * WP;

    // Even-lattice contribution: pair x>>1, half x&1
    const size_t ei = (rowc + (x >> 1)) * 2 + (x & 1);
    const uint2 e = lat2[ei];
    lat2[ei] = make_uint2(0u, 0u);                     // re-zero
    const float2 xyE = __half22float2(u32_to_h2(e.x));
    const float  wE  = __low2float(u32_to_h2(e.y));

    // Odd-lattice contribution: covers x >= 1
    float2 xyO = make_float2(0.f, 0.f);
    float  wO  = 0.f;
    if (x > 0) {
        const int xo = x - 1;
        const size_t oi = ((size_t)LAT1 + rowc + (xo >> 1)) * 2 + (xo & 1);
        const uint2 o = lat2[oi];
        lat2[oi] = make_uint2(0u, 0u);                 // re-zero
        xyO = __half22float2(u32_to_h2(o.x));
        wO  = __low2float(u32_to_h2(o.y));
    }

    const float cnt  = wE + wO;
    const bool  hole = !(cnt > 0.0f);
    const float inv  = 1.0f / (hole ? 1.0f : cnt);

    out[p]      = (xyE.x + xyO.x) * inv;
    out[HW + p] = (xyE.y + xyO.y) * inv;
    g_mask[gbase + p] = hole ? 0 : 1;

    // Compact hole indices: one atomicAdd per warp.
    const unsigned ballot = __ballot_sync(0xffffffffu, hole);
    if (ballot) {
        const int lane   = threadIdx.x & 31;
        const int leader = __ffs(ballot) - 1;
        int base = 0;
        if (lane == leader) base = atomicAdd(&g_hole_count, __popc(ballot));
        base = __shfl_sync(0xffffffffu, base, leader);
        if (hole) {
            const int rank = __popc(ballot & ((1u << lane) - 1u));
            g_holes[base + rank] = gbase + p;
        }
    }
}

// ---------------------------------------------------------------------------
// 3) Hole fill over the compacted list (~2% of pixels): walk 4 axis
//    directions to nearest filled pixel, average. Writes only holes,
//    reads only filled pixels -> race-free in-place.
// ---------------------------------------------------------------------------
__global__ void fill_kernel(float* __restrict__ out) {
    const int n      = g_hole_count;
    const int stride = gridDim.x * blockDim.x;

    for (int j = blockIdx.x * blockDim.x + threadIdx.x; j < n; j += stride) {
        const int i = g_holes[j];
        const int b = i / HW;
        const int p = i - b * HW;
        const int y = p / Wn;
        const int x = p - y * Wn;

        const unsigned char* m  = g_mask + (size_t)b * HW;
        float*               o0 = out + (size_t)b * 2 * HW;
        float*               o1 = o0 + HW;

        float sx = 0.f, sy = 0.f;
        int   s  = 0;

        for (int xx = x - 1; xx >= 0; --xx) {            // left
            int q = y * Wn + xx;
            if (m[q]) { sx += o0[q]; sy += o1[q]; s++; break; }
        }
        for (int xx = x + 1; xx < Wn; ++xx) {            // right
            int q = y * Wn + xx;
            if (m[q]) { sx += o0[q]; sy += o1[q]; s++; break; }
        }
        for (int yy = y - 1; yy >= 0; --yy) {            // up
            int q = yy * Wn + x;
            if (m[q]) { sx += o0[q]; sy += o1[q]; s++; break; }
        }
        for (int yy = y + 1; yy < Hn; ++yy) {            // down
            int q = yy * Wn + x;
            if (m[q]) { sx += o0[q]; sy += o1[q]; s++; break; }
        }

        if (s > 0) {
            const float inv = 1.0f / (float)s;
            o0[y * Wn + x] = sx * inv;
            o1[y * Wn + x] = sy * inv;
        }
        // s == 0: out already 0 at holes (count==0 implies acc.xy==0)
    }
}

// ---------------------------------------------------------------------------
// Launch: per-batch slice pipeline through the L2-resident scratch.
// Lattice zeroing is folded into normalize (self-restoring invariant).
// ---------------------------------------------------------------------------
extern "C" void kernel_launch(void* const* d_in, const int* in_sizes, int n_in,
                              void* d_out, int out_size) {
    const float* flow  = (const float*)d_in[0];   // (B, 2, H, W) fp32
    const float* depth = (const float*)d_in[1];   // (B, 1, H, W) fp32
    float*       out   = (float*)d_out;           // (B, 2, H, W) fp32

    reset_kernel<<<1, 1>>>();

    // HW == 8100 * 256 exactly
    for (int b = 0; b < Bn; ++b) {
        splat_kernel<<<8100, 256>>>(flow + (size_t)b * 2 * HW,
                                    depth + (size_t)b * HW);
        normalize_kernel<<<8100, 256>>>(out + (size_t)b * 2 * HW, b * HW);
    }
    fill_kernel<<<2048, 256>>>(out);
}

// round 8
// speedup vs baseline: 1.3589x; 1.3589x over previous
#include <cuda_runtime.h>
#include <cuda_fp16.h>
#include <cstdint>

// Problem constants (fixed per reference)
#define Bn 8
#define Hn 1080
#define Wn 1920
constexpr int HW   = Hn * Wn;          // 2,073,600
constexpr int BHW  = Bn * HW;          // 16,588,800
constexpr int WP   = Wn / 2;           // 960 pair-cells per row
constexpr int LAT1 = Hn * WP;          // 1,036,800 pair-cells per parity lattice

// DOUBLE-BUFFERED per-slice pair-cell lattices (both slots L2-resident):
// slot s (s=b%2) = [parity0 lattice | parity1 lattice], each LAT1 16B cells.
// Cell = [vx0,vy0,w0,pad | vx1,vy1,w1,pad] (8 x f16).
// Parity 0 (even): pair k covers corners (2k, 2k+1)
// Parity 1 (odd):  pair k covers corners (2k+1, 2k+2)
__device__ float4        g_lat[4 * LAT1];   // 66.4 MB — fits L2 (126 MB)
__device__ unsigned char g_mask[BHW];       // count>0 flag (whole image)
__device__ int           g_holes[BHW];      // compacted hole indices (global index)
__device__ int           g_hole_count;

// --- bit reinterpretation helpers (header-portable) ------------------------
__device__ __forceinline__ unsigned h2_to_u32(__half2 h) {
    union { __half2 h; unsigned u; } cvt; cvt.h = h; return cvt.u;
}
__device__ __forceinline__ __half2 u32_to_h2(unsigned u) {
    union { unsigned u; __half2 h; } cvt; cvt.u = u; return cvt.h;
}

// One 16B vectorized f16x2 reduction: deposits (vx,vy,w) to TWO adjacent corners.
__device__ __forceinline__ void red_add_v4_f16x2(float4* p, unsigned r0, unsigned r1,
                                                 unsigned r2, unsigned r3) {
    asm volatile("red.global.add.noftz.v4.f16x2 [%0], {%1, %2, %3, %4};"
                 :: "l"(p), "r"(r0), "r"(r1), "r"(r2), "r"(r3) : "memory");
}

// ---------------------------------------------------------------------------
// 1) Zero one lattice slot (2*LAT1 float4 == HW cells, grid 8100x256 exact).
//    Full-line zero-writes also RESTORE L2 RESIDENCY of the slot (R7 lesson:
//    without this, splat's REDs fetch evicted lines from DRAM).
// ---------------------------------------------------------------------------
__global__ void zero_kernel(int slot, int reset_counter) {
    int i = blockIdx.x * blockDim.x + threadIdx.x;
    g_lat[(size_t)slot * 2 * LAT1 + i] = make_float4(0.f, 0.f, 0.f, 0.f);
    if (reset_counter && i == 0) g_hole_count = 0;
}

// ---------------------------------------------------------------------------
// 2) Fused pipeline kernel: splat slice b into slot sB, normalize slice b-1
//    from slot sPrev. REDs are fire-and-forget, issued before the normalize
//    loads, so the two latency-bound phases overlap inside each thread.
// ---------------------------------------------------------------------------
__global__ void fused_kernel(const float* __restrict__ flow,    // slice b (or null-ish if !doSplat)
                             const float* __restrict__ depth,   // slice b
                             float* __restrict__ outPrev,       // slice b-1 out base
                             int gbasePrev,                     // (b-1)*HW
                             int sB, int sPrev,
                             int doSplat, int doNorm) {
    const int p = blockIdx.x * blockDim.x + threadIdx.x;   // [0, HW)
    const int y = p / Wn;
    const int x = p - y * Wn;

    // ---------------- Phase A: splat slice b -> slot sB --------------------
    if (doSplat) {
        const float fx = flow[p];
        const float fy = flow[HW + p];

        const float x2 = (float)x + fx;
        const float y2 = (float)y + fy;

        // Invalid pixels deposit exactly 0 in the reference -> skip.
        if (x2 >= 0.0f && x2 <= (float)(Wn - 1) &&
            y2 >= 0.0f && y2 <= (float)(Hn - 1)) {

            const float w  = depth[p];
            const float vx = -fx * w;
            const float vy = -fy * w;

            // floor == trunc (non-negative by validity check)
            const int ixL = (int)x2;
            const int iyT = (int)y2;
            const int ixR = min(ixL + 1, Wn - 1);
            const int iyB = min(iyT + 1, Hn - 1);

            // lo half -> corner ixL, hi half -> corner ixR.
            // ixR==ixL (x2 == W-1 exactly): double lo payload, zero hi
            // (rn(2v) == 2*rn(v) in f16, bit-identical to two adds).
            const bool  dup = (ixR == ixL);
            const float m   = dup ? 2.0f : 1.0f;

            const unsigned r0 = h2_to_u32(__floats2half2_rn(vx * m, vy * m));
            const unsigned r1 = h2_to_u32(__floats2half2_rn(w * m, 0.0f));
            const unsigned r2 = dup ? 0u : h2_to_u32(__floats2half2_rn(vx, vy));
            const unsigned r3 = dup ? 0u : h2_to_u32(__floats2half2_rn(w, 0.0f));

            const int par = ixL & 1;       // parity lattice
            const int kp  = ixL >> 1;      // pair index

            float4* lat = g_lat + (size_t)sB * 2 * LAT1 + (size_t)par * LAT1 + kp;
            red_add_v4_f16x2(lat + iyT * WP, r0, r1, r2, r3);
            red_add_v4_f16x2(lat + iyB * WP, r0, r1, r2, r3);
        }
    }

    // ---------------- Phase B: normalize slice b-1 <- slot sPrev -----------
    if (doNorm) {
        const uint2* lat2 = (const uint2*)(g_lat + (size_t)sPrev * 2 * LAT1);
        const size_t rowc = (size_t)y * WP;

        // Even-parity contribution: pair x>>1, half x&1
        const uint2 e = lat2[(rowc + (x >> 1)) * 2 + (x & 1)];
        const float2 xyE = __half22float2(u32_to_h2(e.x));
        const float  wE  = __low2float(u32_to_h2(e.y));

        // Odd-parity contribution: covers x >= 1
        float2 xyO = make_float2(0.f, 0.f);
        float  wO  = 0.f;
        if (x > 0) {
            const int xo = x - 1;
            const uint2 o = lat2[((size_t)LAT1 + rowc + (xo >> 1)) * 2 + (xo & 1)];
            xyO = __half22float2(u32_to_h2(o.x));
            wO  = __low2float(u32_to_h2(o.y));
        }

        const float cnt  = wE + wO;
        const bool  hole = !(cnt > 0.0f);
        const float inv  = 1.0f / (hole ? 1.0f : cnt);

        outPrev[p]      = (xyE.x + xyO.x) * inv;
        outPrev[HW + p] = (xyE.y + xyO.y) * inv;
        g_mask[gbasePrev + p] = hole ? 0 : 1;

        // Compact hole indices: one atomicAdd per warp.
        const unsigned ballot = __ballot_sync(0xffffffffu, hole);
        if (ballot) {
            const int lane   = threadIdx.x & 31;
            const int leader = __ffs(ballot) - 1;
            int base = 0;
            if (lane == leader) base = atomicAdd(&g_hole_count, __popc(ballot));
            base = __shfl_sync(0xffffffffu, base, leader);
            if (hole) {
                const int rank = __popc(ballot & ((1u << lane) - 1u));
                g_holes[base + rank] = gbasePrev + p;
            }
        }
    }
}

// ---------------------------------------------------------------------------
// 3) Hole fill over the compacted list (~2% of pixels): walk 4 axis
//    directions to nearest filled pixel, average. Writes only holes,
//    reads only filled pixels -> race-free in-place.
// ---------------------------------------------------------------------------
__global__ void fill_kernel(float* __restrict__ out) {
    const int n      = g_hole_count;
    const int stride = gridDim.x * blockDim.x;

    for (int j = blockIdx.x * blockDim.x + threadIdx.x; j < n; j += stride) {
        const int i = g_holes[j];
        const int b = i / HW;
        const int p = i - b * HW;
        const int y = p / Wn;
        const int x = p - y * Wn;

        const unsigned char* m  = g_mask + (size_t)b * HW;
        float*               o0 = out + (size_t)b * 2 * HW;
        float*               o1 = o0 + HW;

        float sx = 0.f, sy = 0.f;
        int   s  = 0;

        for (int xx = x - 1; xx >= 0; --xx) {            // left
            int q = y * Wn + xx;
            if (m[q]) { sx += o0[q]; sy += o1[q]; s++; break; }
        }
        for (int xx = x + 1; xx < Wn; ++xx) {            // right
            int q = y * Wn + xx;
            if (m[q]) { sx += o0[q]; sy += o1[q]; s++; break; }
        }
        for (int yy = y - 1; yy >= 0; --yy) {            // up
            int q = yy * Wn + x;
            if (m[q]) { sx += o0[q]; sy += o1[q]; s++; break; }
        }
        for (int yy = y + 1; yy < Hn; ++yy) {            // down
            int q = yy * Wn + x;
            if (m[q]) { sx += o0[q]; sy += o1[q]; s++; break; }
        }

        if (s > 0) {
            const float inv = 1.0f / (float)s;
            o0[y * Wn + x] = sx * inv;
            o1[y * Wn + x] = sy * inv;
        }
        // s == 0: out already 0 at holes (count==0 implies acc.xy==0)
    }
}

// ---------------------------------------------------------------------------
// Launch: software-pipelined slices through double-buffered L2 scratch.
//   zero(slot b%2); fused(splat b, norm b-1); ... ; fused(norm 7); fill
// ---------------------------------------------------------------------------
extern "C" void kernel_launch(void* const* d_in, const int* in_sizes, int n_in,
                              void* d_out, int out_size) {
    const float* flow  = (const float*)d_in[0];   // (B, 2, H, W) fp32
    const float* depth = (const float*)d_in[1];   // (B, 1, H, W) fp32
    float*       out   = (float*)d_out;           // (B, 2, H, W) fp32

    // HW == 8100 * 256 exactly
    for (int b = 0; b < Bn; ++b) {
        const int sB    = b & 1;
        const int sPrev = (b - 1) & 1;
        zero_kernel<<<8100, 256>>>(sB, b == 0 ? 1 : 0);
        fused_kernel<<<8100, 256>>>(flow + (size_t)b * 2 * HW,
                                    depth + (size_t)b * HW,
                                    b > 0 ? out + (size_t)(b - 1) * 2 * HW : out,
                                    (b - 1) * HW,
                                    sB, sPrev,
                                    /*doSplat=*/1, /*doNorm=*/b > 0 ? 1 : 0);
    }
    // Drain: normalize the last slice (7) from slot 7&1 = 1.
    fused_kernel<<<8100, 256>>>(flow, depth,
                                out + (size_t)(Bn - 1) * 2 * HW,
                                (Bn - 1) * HW,
                                /*sB=*/0, /*sPrev=*/(Bn - 1) & 1,
                                /*doSplat=*/0, /*doNorm=*/1);

    fill_kernel<<<2048, 256>>>(out);
}